// round 14
// baseline (speedup 1.0000x reference)
#include <cuda_runtime.h>
#include <cstdint>

// ---------------------------------------------------------------------------
// CorrelationHead: corr(P=16, DIL=2, H=7, C=256) -> FC(12544->1024) ReLU
//                  -> FC(1024->1024) ReLU -> FC(1024->4)
// 625 live features = same-parity entries of per-RoI Gram X1[49,256]X2^T.
// R14: GEMM CTA tile 128x64 (8 warps 4x2, warp tile 32x32 = 2x4 m16n8k8,
// R8-validated fragment path), 2-stage cp.async (55.3KB -> 4 CTAs/SM),
// both GEMMs split-K z=4. Fused corr+prep; reduce1 folds 4; fc3 folds 4.
// ---------------------------------------------------------------------------

#define NB   1024
#define KC   640
#define KCV  625
#define REP  1024
#define CHUNKF 1568              // 32 ch * 49 pos floats per patch chunk
#define NBREP (NB * REP)

// scratch (static device globals; no allocation allowed)
__device__ float g_corrc[NB * KC];      // compacted correlation (tf32)
__device__ float g_W1c  [REP * KC];     // gathered W1 columns (tf32)
__device__ float g_W2r  [REP * REP];    // W2 (tf32)
__device__ float g_out1 [NB * REP];     // FC1 out (tf32)
__device__ float g_split[4 * NB * REP]; // split-K partials (fp32), reused

// ---------------------------------------------------------------------------
__device__ __forceinline__ float tf32r(float x)
{
    unsigned u;
    asm("cvt.rna.tf32.f32 %0, %1;" : "=r"(u) : "f"(x));
    return __uint_as_float(u);
}
__device__ __forceinline__ unsigned tf32u(float x)
{
    unsigned u;
    asm("cvt.rna.tf32.f32 %0, %1;" : "=r"(u) : "f"(x));
    return u;
}

// compact index u -> (r1, r2) position pair  (class-major ordering)
__device__ __forceinline__ void u_decode(int u, int& r1, int& r2)
{
    int c, rem;
    if      (u < 256) { c = 0; rem = u; }
    else if (u < 400) { c = 1; rem = u - 256; }
    else if (u < 544) { c = 2; rem = u - 400; }
    else              { c = 3; rem = u - 544; }
    int pi = c >> 1, pj = c & 1;
    int ni = pi ? 3 : 4, nj = pj ? 3 : 4;
    int nc = ni * nj;
    int al = rem / nc, bl = rem - al * nc;
    int i  = 2 * (al / nj) + pi, j  = 2 * (al % nj) + pj;
    int i2 = 2 * (bl / nj) + pi, j2 = 2 * (bl % nj) + pj;
    r1 = i * 7 + j;
    r2 = i2 * 7 + j2;
}

__device__ __forceinline__ void cpa16(float* s, const float* g)
{
    unsigned sa = (unsigned)__cvta_generic_to_shared(s);
    asm volatile("cp.async.cg.shared.global [%0], [%1], 16;" :: "r"(sa), "l"(g));
}

__device__ __forceinline__ void mma8(float* c, const unsigned* a, const unsigned* b)
{
    asm volatile(
        "mma.sync.aligned.m16n8k8.row.col.f32.tf32.tf32.f32 "
        "{%0,%1,%2,%3}, {%4,%5,%6,%7}, {%8,%9}, {%0,%1,%2,%3};\n"
        : "+f"(c[0]), "+f"(c[1]), "+f"(c[2]), "+f"(c[3])
        : "r"(a[0]), "r"(a[1]), "r"(a[2]), "r"(a[3]), "r"(b[0]), "r"(b[1]));
}

__device__ __forceinline__ void ldm4(unsigned* r, unsigned saddr)
{
    asm volatile(
        "ldmatrix.sync.aligned.m8n8.x4.shared.b16 {%0,%1,%2,%3}, [%4];"
        : "=r"(r[0]), "=r"(r[1]), "=r"(r[2]), "=r"(r[3]) : "r"(saddr));
}

// ---------------------------------------------------------------------------
// Kernel 1: FUSED corr + prep.  grid 3328 x 128 threads.
//   blocks [0,1024)    : correlation (padded 64x64 Gram, 2-deep pipeline)
//   blocks [1024,2304) : W1 column gather (512 elements each)
//   blocks [2304,3328) : W2 tf32 round (256 float4 each)
// ---------------------------------------------------------------------------
#define CORR_SMEM ((4 * CHUNKF + 16) * 4)   // 25,152 B

__global__ void __launch_bounds__(128)
fused_corr_prep_kernel(const float* __restrict__ p1,
                       const float* __restrict__ p2,
                       const float* __restrict__ W1,
                       const float* __restrict__ W2)
{
    const int bx  = blockIdx.x;
    const int tid = threadIdx.x;

    if (bx >= 2304) {                      // ---- W2 round ----
        int base = (bx - 2304) * 256;
#pragma unroll
        for (int it = 0; it < 2; it++) {
            int q = base + it * 128 + tid;
            if (q < REP * REP / 4) {
                float4 v = ((const float4*)W2)[q];
                v.x = tf32r(v.x); v.y = tf32r(v.y);
                v.z = tf32r(v.z); v.w = tf32r(v.w);
                ((float4*)g_W2r)[q] = v;
            }
        }
        return;
    }
    if (bx >= 1024) {                      // ---- W1 gather ----
        int base = (bx - 1024) * 512;
#pragma unroll
        for (int it = 0; it < 4; it++) {
            int idx = base + it * 128 + tid;
            if (idx < REP * KC) {
                int n = idx / KC;
                int u = idx - n * KC;
                float val = 0.f;
                if (u < KCV) {
                    int r1, r2;
                    u_decode(u, r1, r2);
                    int i = r1 / 7, j = r1 - 7 * i;
                    int i2 = r2 / 7, j2 = r2 - 7 * i2;
                    int ph = ((i2 - i) + 14) >> 1;
                    int pw = ((j2 - j) + 14) >> 1;
                    int col = (ph * 16 + pw) * 49 + r1;
                    val = tf32r(W1[n * 12544 + col]);
                }
                g_W1c[idx] = val;
            }
        }
        return;
    }

    // ---- correlation ----
    extern __shared__ float smem[];

    const int b    = bx;
    const int lane = tid & 31, warp = tid >> 5;
    const int wm   = warp & 1, wn = warp >> 1;
    const int grp  = lane >> 2, qd = lane & 3;
    const float* g1 = p1 + (size_t)b * 12544;
    const float* g2 = p2 + (size_t)b * 12544;

    auto issue = [&](int c) {
        float* s1 = smem + (c & 1) * 2 * CHUNKF;
        float* s2 = s1 + CHUNKF;
        const float* q1 = g1 + c * CHUNKF;
        const float* q2 = g2 + c * CHUNKF;
#pragma unroll
        for (int it = 0; it < 4; it++) {
            int f = tid + it * 128;
            if (f < 392) {
                cpa16(&s1[f * 4], q1 + f * 4);
                cpa16(&s2[f * 4], q2 + f * 4);
            }
        }
        asm volatile("cp.async.commit_group;" ::: "memory");
    };

    issue(0);

    float acc[2][4][4];
#pragma unroll
    for (int mt = 0; mt < 2; mt++)
#pragma unroll
        for (int nt = 0; nt < 4; nt++)
#pragma unroll
            for (int t = 0; t < 4; t++) acc[mt][nt][t] = 0.f;

    for (int c = 0; c < 8; c++) {
        if (c < 7) {
            issue(c + 1);
            asm volatile("cp.async.wait_group 1;" ::: "memory");
        } else {
            asm volatile("cp.async.wait_group 0;" ::: "memory");
        }
        __syncthreads();

        const float* s1 = smem + (c & 1) * 2 * CHUNKF;
        const float* s2 = s1 + CHUNKF;

#pragma unroll
        for (int k8 = 0; k8 < 32; k8 += 8) {
            unsigned af[2][4], bf[4][2];
            const float* k0 = s1 + (k8 + qd) * 49;
            const float* k4 = s1 + (k8 + qd + 4) * 49;
#pragma unroll
            for (int mt = 0; mt < 2; mt++) {
                int r0 = wm * 32 + mt * 16 + grp;
                af[mt][0] = tf32u(k0[r0]);
                af[mt][1] = tf32u(k0[r0 + 8]);
                af[mt][2] = tf32u(k4[r0]);
                af[mt][3] = tf32u(k4[r0 + 8]);
            }
            const float* j0 = s2 + (k8 + qd) * 49;
            const float* j4 = s2 + (k8 + qd + 4) * 49;
#pragma unroll
            for (int nt = 0; nt < 4; nt++) {
                int c0 = wn * 32 + nt * 8 + grp;
                bf[nt][0] = tf32u(j0[c0]);
                bf[nt][1] = tf32u(j4[c0]);
            }
#pragma unroll
            for (int mt = 0; mt < 2; mt++)
#pragma unroll
                for (int nt = 0; nt < 4; nt++)
                    mma8(acc[mt][nt], af[mt], bf[nt]);
        }
        __syncthreads();
    }

    float* gc = g_corrc + (size_t)b * KC;
    if (tid < KC - KCV) gc[KCV + tid] = 0.f;
#pragma unroll
    for (int mt = 0; mt < 2; mt++) {
#pragma unroll
        for (int nt = 0; nt < 4; nt++) {
#pragma unroll
            for (int t = 0; t < 4; t++) {
                int r  = wm * 32 + mt * 16 + grp + (t >> 1) * 8;
                int cc = wn * 32 + nt * 8 + qd * 2 + (t & 1);
                if (r < 49 && cc < 49) {
                    int i = r / 7,  j = r - 7 * i;
                    int i2 = cc / 7, j2 = cc - 7 * i2;
                    if ((((i ^ i2) | (j ^ j2)) & 1) == 0) {
                        int pi = i & 1, pj = j & 1;
                        int nj = pj ? 3 : 4;
                        int nc = (pi ? 3 : 4) * nj;
                        int off = pi ? (pj ? 544 : 400) : (pj ? 256 : 0);
                        int al = (i >> 1) * nj + (j >> 1);
                        int bl = (i2 >> 1) * nj + (j2 >> 1);
                        gc[off + al * nc + bl] = tf32r(acc[mt][nt][t]);
                    }
                }
            }
        }
    }
}

// ---------------------------------------------------------------------------
// Kernel 2/4: tf32 GEMM, CTA tile 128x64, ldmatrix fragments, 256 threads,
// 2-stage cp.async. 8 warps (4x2), warp tile 32x32 (2x4 m16n8k8).
// Per k8: 4 ldm.x4 + 8 mma (256 B smem read per mma).
// smem 55.3KB -> 4 CTAs/SM. Writes RAW fp32 partials to g_split[z].
// MODE 2 (FC1): A=g_corrc+z*KLEN (stride 640), B=g_W1c+z*KLEN.
// MODE 1 (FC2): A=g_out1 +z*KLEN (stride 1024), B=g_W2r+z*KLEN.
// ---------------------------------------------------------------------------
#define ASTG (128 * 36)
#define BSTG (64 * 36)
#define SSTG (ASTG + BSTG)
#define GEMM_SMEM (2 * SSTG * 4)   // 55,296 B

template <int KLEN, int MODE>
__global__ void __launch_bounds__(256, 4)
gemm_tf32_kernel()
{
    const int KROW = (MODE == 2) ? KC : REP;
    const int kofs = blockIdx.z * KLEN;
    const float* A  = ((MODE == 2) ? g_corrc : g_out1) + kofs;
    const float* Bm = ((MODE == 2) ? g_W1c   : g_W2r ) + kofs;
    float*       Cm = g_split + (size_t)blockIdx.z * NBREP;

    extern __shared__ float sm[];
    const unsigned smu = (unsigned)__cvta_generic_to_shared(sm);

    const int tid  = threadIdx.x;
    const int warp = tid >> 5, lane = tid & 31;
    const int wm   = warp & 3, wn = warp >> 2;      // 4 x 2 warp grid
    const int grp  = lane >> 2, qd = lane & 3;

    // loaders: A 128 rows x 32 floats (1024 f4, 4/thr); B 64 rows (512 f4, 2/thr)
    const int arow = tid >> 1,  ac0 = (tid & 1) * 16;
    const int brow = tid >> 2,  bc0 = (tid & 3) * 8;
    const float* Ag = A  + (size_t)(blockIdx.y * 128 + arow) * KROW + ac0;
    const float* Bg = Bm + (size_t)(blockIdx.x *  64 + brow) * KROW + bc0;

    // ldmatrix lane addressing (R8-validated)
    const int lrow16 = lane & 15;
    const int lhw    = (lane >> 4) * 4;
    const unsigned aofs0 = (unsigned)((wm * 32 + lrow16) * 36 + lhw) * 4;
    const unsigned aofs1 = aofs0 + 16 * 36 * 4;
    const unsigned bofs0 = (unsigned)((wn * 32 + lrow16) * 36 + lhw) * 4;
    const unsigned bofs1 = bofs0 + 16 * 36 * 4;

    float acc[2][4][4];
#pragma unroll
    for (int mt = 0; mt < 2; mt++)
#pragma unroll
        for (int nt = 0; nt < 4; nt++)
#pragma unroll
            for (int t = 0; t < 4; t++) acc[mt][nt][t] = 0.f;

    const int NT = KLEN / 32;

    auto issue = [&](int kt) {
        if (kt < NT) {
            float* as = sm + (kt & 1) * SSTG;
            float* bs = as + ASTG;
#pragma unroll
            for (int q = 0; q < 4; q++)
                cpa16(&as[arow * 36 + ac0 + q * 4], Ag + kt * 32 + q * 4);
#pragma unroll
            for (int q = 0; q < 2; q++)
                cpa16(&bs[brow * 36 + bc0 + q * 4], Bg + kt * 32 + q * 4);
        }
        asm volatile("cp.async.commit_group;" ::: "memory");
    };

    issue(0); issue(1);

    for (int kt = 0; kt < NT; kt++) {
        asm volatile("cp.async.wait_group 1;" ::: "memory");
        __syncthreads();

        const unsigned sa = smu + (unsigned)(kt & 1) * SSTG * 4;
        const unsigned sb = sa + ASTG * 4;
#pragma unroll
        for (int k8 = 0; k8 < 32; k8 += 8) {
            unsigned af[2][4], t0[4], t1[4];
            ldm4(af[0], sa + aofs0 + k8 * 4);
            ldm4(af[1], sa + aofs1 + k8 * 4);
            ldm4(t0,    sb + bofs0 + k8 * 4);
            ldm4(t1,    sb + bofs1 + k8 * 4);
            unsigned bf[4][2] = { {t0[0], t0[2]}, {t0[1], t0[3]},
                                  {t1[0], t1[2]}, {t1[1], t1[3]} };
#pragma unroll
            for (int mt = 0; mt < 2; mt++)
#pragma unroll
                for (int nt = 0; nt < 4; nt++)
                    mma8(acc[mt][nt], af[mt], bf[nt]);
        }
        __syncthreads();
        issue(kt + 2);
    }

    // epilogue: raw fp32 partial stores
#pragma unroll
    for (int mt = 0; mt < 2; mt++) {
#pragma unroll
        for (int nt = 0; nt < 4; nt++) {
            int rg = blockIdx.y * 128 + wm * 32 + mt * 16 + grp;
            int cg = blockIdx.x *  64 + wn * 32 + nt * 8 + qd * 2;
#pragma unroll
            for (int h = 0; h < 2; h++) {
                float v0 = acc[mt][nt][h * 2 + 0];
                float v1 = acc[mt][nt][h * 2 + 1];
                *(float2*)&Cm[(size_t)(rg + h * 8) * 1024 + cg] = make_float2(v0, v1);
            }
        }
    }
}

// ---------------------------------------------------------------------------
// Kernel 3: FC1 4-way split-K reduce + bias + ReLU + tf32 round -> g_out1
// ---------------------------------------------------------------------------
__global__ void __launch_bounds__(256)
reduce_fc1_kernel(const float* __restrict__ b1)
{
    int q = blockIdx.x * 256 + threadIdx.x;     // float4 index
    if (q >= NBREP / 4) return;
    float4 a = ((const float4*)g_split)[q];
    float4 b = ((const float4*)(g_split + NBREP))[q];
    float4 c = ((const float4*)(g_split + 2 * (size_t)NBREP))[q];
    float4 d = ((const float4*)(g_split + 3 * (size_t)NBREP))[q];
    float4 bb = *(const float4*)&b1[(q & 255) * 4];
    float4 r;
    r.x = tf32r(fmaxf((a.x + b.x) + (c.x + d.x) + bb.x, 0.f));
    r.y = tf32r(fmaxf((a.y + b.y) + (c.y + d.y) + bb.y, 0.f));
    r.z = tf32r(fmaxf((a.z + b.z) + (c.z + d.z) + bb.z, 0.f));
    r.w = tf32r(fmaxf((a.w + b.w) + (c.w + d.w) + bb.w, 0.f));
    ((float4*)g_out1)[q] = r;
}

// ---------------------------------------------------------------------------
// Kernel 5: FC3 fused with FC2 4-way split-K reduce + bias + ReLU.
// ---------------------------------------------------------------------------
__global__ void __launch_bounds__(128)
fc3_kernel(const float* __restrict__ b2, const float* __restrict__ W3,
           const float* __restrict__ b3, float* __restrict__ out)
{
    __shared__ float xs[1024];
    int b    = blockIdx.x;
    int tid  = threadIdx.x;
    int warp = tid >> 5;
    int lane = tid & 31;

    const float* s0 = g_split + (size_t)b * 1024;
#pragma unroll
    for (int it = 0; it < 2; it++) {
        int q = tid + it * 128;           // float4 index 0..255
        float4 a = ((const float4*)s0)[q];
        float4 c = ((const float4*)(s0 + NBREP))[q];
        float4 d = ((const float4*)(s0 + 2 * (size_t)NBREP))[q];
        float4 e = ((const float4*)(s0 + 3 * (size_t)NBREP))[q];
        float4 bb = *(const float4*)&b2[q * 4];
        float4 r;
        r.x = fmaxf((a.x + c.x) + (d.x + e.x) + bb.x, 0.f);
        r.y = fmaxf((a.y + c.y) + (d.y + e.y) + bb.y, 0.f);
        r.z = fmaxf((a.z + c.z) + (d.z + e.z) + bb.z, 0.f);
        r.w = fmaxf((a.w + c.w) + (d.w + e.w) + bb.w, 0.f);
        *(float4*)&xs[q * 4] = r;
    }
    __syncthreads();

    const float* w = W3 + warp * 1024;
    float acc = 0.f;
#pragma unroll 8
    for (int k = lane; k < 1024; k += 32) acc += xs[k] * w[k];
#pragma unroll
    for (int off = 16; off; off >>= 1)
        acc += __shfl_xor_sync(0xffffffffu, acc, off);
    if (lane == 0) out[b * 4 + warp] = acc + b3[warp];
}

// ---------------------------------------------------------------------------
// launch  (gemm2 is the 4th launch -> it gets profiled)
// ---------------------------------------------------------------------------
extern "C" void kernel_launch(void* const* d_in, const int* in_sizes, int n_in,
                              void* d_out, int out_size)
{
    const float* p1 = (const float*)d_in[0];
    const float* p2 = (const float*)d_in[1];
    const float* W1 = (const float*)d_in[2];
    const float* b1 = (const float*)d_in[3];
    const float* W2 = (const float*)d_in[4];
    const float* b2 = (const float*)d_in[5];
    const float* W3 = (const float*)d_in[6];
    const float* b3 = (const float*)d_in[7];
    float* out = (float*)d_out;
    (void)in_sizes; (void)n_in; (void)out_size;

    cudaFuncSetAttribute(fused_corr_prep_kernel,
                         cudaFuncAttributeMaxDynamicSharedMemorySize, CORR_SMEM);
    cudaFuncSetAttribute(gemm_tf32_kernel<160, 2>,
                         cudaFuncAttributeMaxDynamicSharedMemorySize, GEMM_SMEM);
    cudaFuncSetAttribute(gemm_tf32_kernel<256, 1>,
                         cudaFuncAttributeMaxDynamicSharedMemorySize, GEMM_SMEM);

    fused_corr_prep_kernel<<<3328, 128, CORR_SMEM>>>(p1, p2, W1, W2);       // 1
    gemm_tf32_kernel<160, 2><<<dim3(16, 8, 4), 256, GEMM_SMEM>>>();         // 2
    reduce_fc1_kernel<<<NBREP / 4 / 256, 256>>>(b1);                        // 3
    gemm_tf32_kernel<256, 1><<<dim3(16, 8, 4), 256, GEMM_SMEM>>>();         // 4 (profiled)
    fc3_kernel<<<NB, 128>>>(b2, W3, b3, out);                               // 5
}

// round 16
// speedup vs baseline: 1.2543x; 1.2543x over previous
#include <cuda_runtime.h>
#include <cuda_fp16.h>
#include <cstdint>

// ---------------------------------------------------------------------------
// CorrelationHead: corr(P=16, DIL=2, H=7, C=256) -> FC(12544->1024) ReLU
//                  -> FC(1024->1024) ReLU -> FC(1024->4)
// 625 live features = same-parity entries of per-RoI Gram X1[49,256]X2^T.
// R16 (= R15 resubmit; prior round was an infra failure): R11 structure
// (fused corr+prep, FC1 tf32 z=2) with FC2 switched to fp16 operands / fp32
// accumulate (m16n8k16) to halve the cp.async issue count that binds the
// GEMM. fc3 folds 2 partials.
// ---------------------------------------------------------------------------

#define NB   1024
#define KC   640
#define KCV  625
#define REP  1024
#define CHUNKF 1568              // 32 ch * 49 pos floats per patch chunk
#define NBREP (NB * REP)

// scratch (static device globals; no allocation allowed)
__device__ float  g_corrc[NB * KC];      // compacted correlation (tf32)
__device__ float  g_W1c  [REP * KC];     // gathered W1 columns (tf32)
__device__ __half g_W2h  [REP * REP];    // W2 (fp16)
__device__ __half g_out1h[NB * REP];     // FC1 out (fp16)
__device__ float  g_split[2 * NB * REP]; // split-K partials (fp32), reused

// ---------------------------------------------------------------------------
__device__ __forceinline__ float tf32r(float x)
{
    unsigned u;
    asm("cvt.rna.tf32.f32 %0, %1;" : "=r"(u) : "f"(x));
    return __uint_as_float(u);
}
__device__ __forceinline__ unsigned tf32u(float x)
{
    unsigned u;
    asm("cvt.rna.tf32.f32 %0, %1;" : "=r"(u) : "f"(x));
    return u;
}

// compact index u -> (r1, r2) position pair  (class-major ordering)
__device__ __forceinline__ void u_decode(int u, int& r1, int& r2)
{
    int c, rem;
    if      (u < 256) { c = 0; rem = u; }
    else if (u < 400) { c = 1; rem = u - 256; }
    else if (u < 544) { c = 2; rem = u - 400; }
    else              { c = 3; rem = u - 544; }
    int pi = c >> 1, pj = c & 1;
    int ni = pi ? 3 : 4, nj = pj ? 3 : 4;
    int nc = ni * nj;
    int al = rem / nc, bl = rem - al * nc;
    int i  = 2 * (al / nj) + pi, j  = 2 * (al % nj) + pj;
    int i2 = 2 * (bl / nj) + pi, j2 = 2 * (bl % nj) + pj;
    r1 = i * 7 + j;
    r2 = i2 * 7 + j2;
}

__device__ __forceinline__ void cpa16(void* s, const void* g)
{
    unsigned sa = (unsigned)__cvta_generic_to_shared(s);
    asm volatile("cp.async.cg.shared.global [%0], [%1], 16;" :: "r"(sa), "l"(g));
}

__device__ __forceinline__ void mma8(float* c, const unsigned* a, const unsigned* b)
{
    asm volatile(
        "mma.sync.aligned.m16n8k8.row.col.f32.tf32.tf32.f32 "
        "{%0,%1,%2,%3}, {%4,%5,%6,%7}, {%8,%9}, {%0,%1,%2,%3};\n"
        : "+f"(c[0]), "+f"(c[1]), "+f"(c[2]), "+f"(c[3])
        : "r"(a[0]), "r"(a[1]), "r"(a[2]), "r"(a[3]), "r"(b[0]), "r"(b[1]));
}

__device__ __forceinline__ void mma16h(float* c, const unsigned* a, const unsigned* b)
{
    asm volatile(
        "mma.sync.aligned.m16n8k16.row.col.f32.f16.f16.f32 "
        "{%0,%1,%2,%3}, {%4,%5,%6,%7}, {%8,%9}, {%0,%1,%2,%3};\n"
        : "+f"(c[0]), "+f"(c[1]), "+f"(c[2]), "+f"(c[3])
        : "r"(a[0]), "r"(a[1]), "r"(a[2]), "r"(a[3]), "r"(b[0]), "r"(b[1]));
}

__device__ __forceinline__ void ldm4(unsigned* r, unsigned saddr)
{
    asm volatile(
        "ldmatrix.sync.aligned.m8n8.x4.shared.b16 {%0,%1,%2,%3}, [%4];"
        : "=r"(r[0]), "=r"(r[1]), "=r"(r[2]), "=r"(r[3]) : "r"(saddr));
}

// ---------------------------------------------------------------------------
// Kernel 1: FUSED corr + prep.  grid 3328 x 128 threads.
//   blocks [0,1024)    : correlation (padded 64x64 Gram, 2-deep pipeline)
//   blocks [1024,2304) : W1 column gather (tf32)
//   blocks [2304,3328) : W2 fp16 convert
// ---------------------------------------------------------------------------
#define CORR_SMEM ((4 * CHUNKF + 16) * 4)   // 25,152 B

__global__ void __launch_bounds__(128)
fused_corr_prep_kernel(const float* __restrict__ p1,
                       const float* __restrict__ p2,
                       const float* __restrict__ W1,
                       const float* __restrict__ W2)
{
    const int bx  = blockIdx.x;
    const int tid = threadIdx.x;

    if (bx >= 2304) {                      // ---- W2 fp16 convert ----
        int base = (bx - 2304) * 256;
#pragma unroll
        for (int it = 0; it < 2; it++) {
            int q = base + it * 128 + tid;
            if (q < REP * REP / 4) {
                float4 v = ((const float4*)W2)[q];
                __half2* dst = (__half2*)g_W2h + q * 2;
                dst[0] = __floats2half2_rn(v.x, v.y);
                dst[1] = __floats2half2_rn(v.z, v.w);
            }
        }
        return;
    }
    if (bx >= 1024) {                      // ---- W1 gather ----
        int base = (bx - 1024) * 512;
#pragma unroll
        for (int it = 0; it < 4; it++) {
            int idx = base + it * 128 + tid;
            if (idx < REP * KC) {
                int n = idx / KC;
                int u = idx - n * KC;
                float val = 0.f;
                if (u < KCV) {
                    int r1, r2;
                    u_decode(u, r1, r2);
                    int i = r1 / 7, j = r1 - 7 * i;
                    int i2 = r2 / 7, j2 = r2 - 7 * i2;
                    int ph = ((i2 - i) + 14) >> 1;
                    int pw = ((j2 - j) + 14) >> 1;
                    int col = (ph * 16 + pw) * 49 + r1;
                    val = tf32r(W1[n * 12544 + col]);
                }
                g_W1c[idx] = val;
            }
        }
        return;
    }

    // ---- correlation ----
    extern __shared__ float smem[];

    const int b    = bx;
    const int lane = tid & 31, warp = tid >> 5;
    const int wm   = warp & 1, wn = warp >> 1;
    const int grp  = lane >> 2, qd = lane & 3;
    const float* g1 = p1 + (size_t)b * 12544;
    const float* g2 = p2 + (size_t)b * 12544;

    auto issue = [&](int c) {
        float* s1 = smem + (c & 1) * 2 * CHUNKF;
        float* s2 = s1 + CHUNKF;
        const float* q1 = g1 + c * CHUNKF;
        const float* q2 = g2 + c * CHUNKF;
#pragma unroll
        for (int it = 0; it < 4; it++) {
            int f = tid + it * 128;
            if (f < 392) {
                cpa16(&s1[f * 4], q1 + f * 4);
                cpa16(&s2[f * 4], q2 + f * 4);
            }
        }
        asm volatile("cp.async.commit_group;" ::: "memory");
    };

    issue(0);

    float acc[2][4][4];
#pragma unroll
    for (int mt = 0; mt < 2; mt++)
#pragma unroll
        for (int nt = 0; nt < 4; nt++)
#pragma unroll
            for (int t = 0; t < 4; t++) acc[mt][nt][t] = 0.f;

    for (int c = 0; c < 8; c++) {
        if (c < 7) {
            issue(c + 1);
            asm volatile("cp.async.wait_group 1;" ::: "memory");
        } else {
            asm volatile("cp.async.wait_group 0;" ::: "memory");
        }
        __syncthreads();

        const float* s1 = smem + (c & 1) * 2 * CHUNKF;
        const float* s2 = s1 + CHUNKF;

#pragma unroll
        for (int k8 = 0; k8 < 32; k8 += 8) {
            unsigned af[2][4], bf[4][2];
            const float* k0 = s1 + (k8 + qd) * 49;
            const float* k4 = s1 + (k8 + qd + 4) * 49;
#pragma unroll
            for (int mt = 0; mt < 2; mt++) {
                int r0 = wm * 32 + mt * 16 + grp;
                af[mt][0] = tf32u(k0[r0]);
                af[mt][1] = tf32u(k0[r0 + 8]);
                af[mt][2] = tf32u(k4[r0]);
                af[mt][3] = tf32u(k4[r0 + 8]);
            }
            const float* j0 = s2 + (k8 + qd) * 49;
            const float* j4 = s2 + (k8 + qd + 4) * 49;
#pragma unroll
            for (int nt = 0; nt < 4; nt++) {
                int c0 = wn * 32 + nt * 8 + grp;
                bf[nt][0] = tf32u(j0[c0]);
                bf[nt][1] = tf32u(j4[c0]);
            }
#pragma unroll
            for (int mt = 0; mt < 2; mt++)
#pragma unroll
                for (int nt = 0; nt < 4; nt++)
                    mma8(acc[mt][nt], af[mt], bf[nt]);
        }
        __syncthreads();
    }

    float* gc = g_corrc + (size_t)b * KC;
    if (tid < KC - KCV) gc[KCV + tid] = 0.f;
#pragma unroll
    for (int mt = 0; mt < 2; mt++) {
#pragma unroll
        for (int nt = 0; nt < 4; nt++) {
#pragma unroll
            for (int t = 0; t < 4; t++) {
                int r  = wm * 32 + mt * 16 + grp + (t >> 1) * 8;
                int cc = wn * 32 + nt * 8 + qd * 2 + (t & 1);
                if (r < 49 && cc < 49) {
                    int i = r / 7,  j = r - 7 * i;
                    int i2 = cc / 7, j2 = cc - 7 * i2;
                    if ((((i ^ i2) | (j ^ j2)) & 1) == 0) {
                        int pi = i & 1, pj = j & 1;
                        int nj = pj ? 3 : 4;
                        int nc = (pi ? 3 : 4) * nj;
                        int off = pi ? (pj ? 544 : 400) : (pj ? 256 : 0);
                        int al = (i >> 1) * nj + (j >> 1);
                        int bl = (i2 >> 1) * nj + (j2 >> 1);
                        gc[off + al * nc + bl] = tf32r(acc[mt][nt][t]);
                    }
                }
            }
        }
    }
}

// ---------------------------------------------------------------------------
// Kernel 2: FC1 tf32 GEMM (R11-proven). 64x64x32, 256 thr, 8 warps (2x4),
// warp 32x16, ldmatrix, 3-stage cp.async. split-K z=2 (KLEN=320), raw
// partials to g_split[z].
// ---------------------------------------------------------------------------
#define STG  (64 * 36)
#define GEMM1_SMEM (6 * STG * 4)   // 55,296 B

template <int KLEN>
__global__ void __launch_bounds__(256)
gemm1_tf32_kernel()
{
    const int kofs = blockIdx.z * KLEN;
    const float* A  = g_corrc + kofs;
    const float* Bm = g_W1c   + kofs;
    float*       Cm = g_split + (size_t)blockIdx.z * NBREP;

    extern __shared__ float sm[];
    const unsigned smu = (unsigned)__cvta_generic_to_shared(sm);

    const int tid  = threadIdx.x;
    const int warp = tid >> 5, lane = tid & 31;
    const int wm   = warp & 1, wn = warp >> 1;
    const int grp  = lane >> 2, qd = lane & 3;

    const int lrow = tid >> 2;
    const int lc0  = (tid & 3) * 8;
    const float* Ag = A  + (size_t)(blockIdx.y * 64 + lrow) * KC + lc0;
    const float* Bg = Bm + (size_t)(blockIdx.x * 64 + lrow) * KC + lc0;

    const int lrow16 = lane & 15;
    const int lhw    = (lane >> 4) * 4;
    const unsigned aofs0 = (unsigned)((wm * 32 + lrow16) * 36 + lhw) * 4;
    const unsigned aofs1 = aofs0 + 16 * 36 * 4;
    const unsigned bofs  = (unsigned)((wn * 16 + lrow16) * 36 + lhw) * 4;

    float acc[2][2][4];
#pragma unroll
    for (int mt = 0; mt < 2; mt++)
#pragma unroll
        for (int nt = 0; nt < 2; nt++)
#pragma unroll
            for (int t = 0; t < 4; t++) acc[mt][nt][t] = 0.f;

    const int NT = KLEN / 32;

    auto issue = [&](int kt) {
        if (kt < NT) {
            int s = kt % 3;
            float* as = sm + s * 2 * STG;
            float* bs = as + STG;
            cpa16(&as[lrow * 36 + lc0],     Ag + kt * 32);
            cpa16(&as[lrow * 36 + lc0 + 4], Ag + kt * 32 + 4);
            cpa16(&bs[lrow * 36 + lc0],     Bg + kt * 32);
            cpa16(&bs[lrow * 36 + lc0 + 4], Bg + kt * 32 + 4);
        }
        asm volatile("cp.async.commit_group;" ::: "memory");
    };

    issue(0); issue(1);

    for (int kt = 0; kt < NT; kt++) {
        asm volatile("cp.async.wait_group 1;" ::: "memory");
        __syncthreads();
        issue(kt + 2);

        const unsigned sa = smu + (unsigned)(kt % 3) * 2 * STG * 4;
        const unsigned sb = sa + STG * 4;
#pragma unroll
        for (int k8 = 0; k8 < 32; k8 += 8) {
            unsigned af[2][4], t[4];
            ldm4(af[0], sa + aofs0 + k8 * 4);
            ldm4(af[1], sa + aofs1 + k8 * 4);
            ldm4(t,     sb + bofs  + k8 * 4);
            unsigned bf[2][2] = { {t[0], t[2]}, {t[1], t[3]} };
#pragma unroll
            for (int mt = 0; mt < 2; mt++)
#pragma unroll
                for (int nt = 0; nt < 2; nt++)
                    mma8(acc[mt][nt], af[mt], bf[nt]);
        }
    }

#pragma unroll
    for (int mt = 0; mt < 2; mt++) {
#pragma unroll
        for (int nt = 0; nt < 2; nt++) {
            int rg = blockIdx.y * 64 + wm * 32 + mt * 16 + grp;
            int cg = blockIdx.x * 64 + wn * 16 + nt * 8 + qd * 2;
#pragma unroll
            for (int h = 0; h < 2; h++) {
                float v0 = acc[mt][nt][h * 2 + 0];
                float v1 = acc[mt][nt][h * 2 + 1];
                *(float2*)&Cm[(size_t)(rg + h * 8) * 1024 + cg] = make_float2(v0, v1);
            }
        }
    }
}

// ---------------------------------------------------------------------------
// Kernel 3: FC1 split-K reduce + bias + ReLU -> fp16 g_out1h
// ---------------------------------------------------------------------------
__global__ void __launch_bounds__(256)
reduce_fc1_kernel(const float* __restrict__ b1)
{
    int q = blockIdx.x * 256 + threadIdx.x;     // float4 index
    if (q >= NBREP / 4) return;
    float4 a = ((const float4*)g_split)[q];
    float4 b = ((const float4*)(g_split + NBREP))[q];
    float4 bb = *(const float4*)&b1[(q & 255) * 4];
    float rx = fmaxf(a.x + b.x + bb.x, 0.f);
    float ry = fmaxf(a.y + b.y + bb.y, 0.f);
    float rz = fmaxf(a.z + b.z + bb.z, 0.f);
    float rw = fmaxf(a.w + b.w + bb.w, 0.f);
    __half2* dst = (__half2*)g_out1h + q * 2;
    dst[0] = __floats2half2_rn(rx, ry);
    dst[1] = __floats2half2_rn(rz, rw);
}

// ---------------------------------------------------------------------------
// Kernel 4: FC2 fp16 GEMM. 64x64 tile, BK=64 halves, 256 thr, 8 warps (2x4),
// warp tile 32x16 (2x2 m16n8k16), ldmatrix, 3-stage cp.async, split-K z=2
// (KLEN=512, NT=8). smem rows padded to 72 halves (144B, ldm conflict-free).
// Raw fp32 partials to g_split[z].
// ---------------------------------------------------------------------------
#define HSTR 72
#define HSTG (64 * HSTR)                     // halves per matrix per stage
#define GEMM2_SMEM (3 * 2 * HSTG * 2)        // 3 stages x (A+B) x 2B = 55,296 B

template <int KLEN>
__global__ void __launch_bounds__(256)
gemm2_fp16_kernel()
{
    const int kofs = blockIdx.z * KLEN;
    const __half* A  = g_out1h + kofs;
    const __half* Bm = g_W2h   + kofs;
    float*        Cm = g_split + (size_t)blockIdx.z * NBREP;

    extern __shared__ __half smh[];
    const unsigned smu = (unsigned)__cvta_generic_to_shared(smh);

    const int tid  = threadIdx.x;
    const int warp = tid >> 5, lane = tid & 31;
    const int wm   = warp & 1, wn = warp >> 1;      // 2 x 4 warp grid
    const int grp  = lane >> 2, qd = lane & 3;

    // loader: 64 rows x 64 halves per matrix per stage; thread: 2+2 cpa16
    const int lrow = tid >> 2;            // 0..63
    const int hc0  = (tid & 3) * 16;      // half offset 0,16,32,48
    const __half* Ag = A  + (size_t)(blockIdx.y * 64 + lrow) * REP + hc0;
    const __half* Bg = Bm + (size_t)(blockIdx.x * 64 + lrow) * REP + hc0;

    // ldmatrix lane addressing: row = base + (lane&15), 16B col = (lane>>4)
    const int lrow16 = lane & 15;
    const int lhb    = (lane >> 4) * 16;  // byte offset within k16 block
    const unsigned aofs0 = (unsigned)(wm * 32 + lrow16) * (HSTR * 2) + lhb;
    const unsigned aofs1 = aofs0 + 16 * HSTR * 2;
    const unsigned bofs  = (unsigned)(wn * 16 + lrow16) * (HSTR * 2) + lhb;

    float acc[2][2][4];
#pragma unroll
    for (int mt = 0; mt < 2; mt++)
#pragma unroll
        for (int nt = 0; nt < 2; nt++)
#pragma unroll
            for (int t = 0; t < 4; t++) acc[mt][nt][t] = 0.f;

    const int NT = KLEN / 64;

    auto issue = [&](int kt) {
        if (kt < NT) {
            __half* as = smh + (kt % 3) * 2 * HSTG;
            __half* bs = as + HSTG;
            cpa16(&as[lrow * HSTR + hc0],     Ag + kt * 64);
            cpa16(&as[lrow * HSTR + hc0 + 8], Ag + kt * 64 + 8);
            cpa16(&bs[lrow * HSTR + hc0],     Bg + kt * 64);
            cpa16(&bs[lrow * HSTR + hc0 + 8], Bg + kt * 64 + 8);
        }
        asm volatile("cp.async.commit_group;" ::: "memory");
    };

    issue(0); issue(1);

    for (int kt = 0; kt < NT; kt++) {
        asm volatile("cp.async.wait_group 1;" ::: "memory");
        __syncthreads();
        issue(kt + 2);

        const unsigned sa = smu + (unsigned)(kt % 3) * 2 * HSTG * 2;
        const unsigned sb = sa + HSTG * 2;
#pragma unroll
        for (int s = 0; s < 4; s++) {       // four k16 steps per BK=64
            unsigned af[2][4], t[4];
            ldm4(af[0], sa + aofs0 + s * 32);
            ldm4(af[1], sa + aofs1 + s * 32);
            ldm4(t,     sb + bofs  + s * 32);
            unsigned bf[2][2] = { {t[0], t[2]}, {t[1], t[3]} };
#pragma unroll
            for (int mt = 0; mt < 2; mt++)
#pragma unroll
                for (int nt = 0; nt < 2; nt++)
                    mma16h(acc[mt][nt], af[mt], bf[nt]);
        }
    }

#pragma unroll
    for (int mt = 0; mt < 2; mt++) {
#pragma unroll
        for (int nt = 0; nt < 2; nt++) {
            int rg = blockIdx.y * 64 + wm * 32 + mt * 16 + grp;
            int cg = blockIdx.x * 64 + wn * 16 + nt * 8 + qd * 2;
#pragma unroll
            for (int h = 0; h < 2; h++) {
                float v0 = acc[mt][nt][h * 2 + 0];
                float v1 = acc[mt][nt][h * 2 + 1];
                *(float2*)&Cm[(size_t)(rg + h * 8) * 1024 + cg] = make_float2(v0, v1);
            }
        }
    }
}

// ---------------------------------------------------------------------------
// Kernel 5: FC3 fused with FC2 2-way split-K reduce + bias + ReLU.
// ---------------------------------------------------------------------------
__global__ void __launch_bounds__(128)
fc3_kernel(const float* __restrict__ b2, const float* __restrict__ W3,
           const float* __restrict__ b3, float* __restrict__ out)
{
    __shared__ float xs[1024];
    int b    = blockIdx.x;
    int tid  = threadIdx.x;
    int warp = tid >> 5;
    int lane = tid & 31;

    const float* s0 = g_split + (size_t)b * 1024;
#pragma unroll
    for (int it = 0; it < 2; it++) {
        int q = tid + it * 128;           // float4 index 0..255
        float4 a = ((const float4*)s0)[q];
        float4 c = ((const float4*)(s0 + NBREP))[q];
        float4 bb = *(const float4*)&b2[q * 4];
        float4 r;
        r.x = fmaxf(a.x + c.x + bb.x, 0.f);
        r.y = fmaxf(a.y + c.y + bb.y, 0.f);
        r.z = fmaxf(a.z + c.z + bb.z, 0.f);
        r.w = fmaxf(a.w + c.w + bb.w, 0.f);
        *(float4*)&xs[q * 4] = r;
    }
    __syncthreads();

    const float* w = W3 + warp * 1024;
    float acc = 0.f;
#pragma unroll 8
    for (int k = lane; k < 1024; k += 32) acc += xs[k] * w[k];
#pragma unroll
    for (int off = 16; off; off >>= 1)
        acc += __shfl_xor_sync(0xffffffffu, acc, off);
    if (lane == 0) out[b * 4 + warp] = acc + b3[warp];
}

// ---------------------------------------------------------------------------
// launch  (gemm2 fp16 is the 4th launch -> it gets profiled)
// ---------------------------------------------------------------------------
extern "C" void kernel_launch(void* const* d_in, const int* in_sizes, int n_in,
                              void* d_out, int out_size)
{
    const float* p1 = (const float*)d_in[0];
    const float* p2 = (const float*)d_in[1];
    const float* W1 = (const float*)d_in[2];
    const float* b1 = (const float*)d_in[3];
    const float* W2 = (const float*)d_in[4];
    const float* b2 = (const float*)d_in[5];
    const float* W3 = (const float*)d_in[6];
    const float* b3 = (const float*)d_in[7];
    float* out = (float*)d_out;
    (void)in_sizes; (void)n_in; (void)out_size;

    cudaFuncSetAttribute(fused_corr_prep_kernel,
                         cudaFuncAttributeMaxDynamicSharedMemorySize, CORR_SMEM);
    cudaFuncSetAttribute(gemm1_tf32_kernel<320>,
                         cudaFuncAttributeMaxDynamicSharedMemorySize, GEMM1_SMEM);
    cudaFuncSetAttribute(gemm2_fp16_kernel<512>,
                         cudaFuncAttributeMaxDynamicSharedMemorySize, GEMM2_SMEM);

    fused_corr_prep_kernel<<<3328, 128, CORR_SMEM>>>(p1, p2, W1, W2);        // 1
    gemm1_tf32_kernel<320><<<dim3(16, 16, 2), 256, GEMM1_SMEM>>>();          // 2
    reduce_fc1_kernel<<<NBREP / 4 / 256, 256>>>(b1);                         // 3
    gemm2_fp16_kernel<512><<<dim3(16, 16, 2), 256, GEMM2_SMEM>>>();          // 4 (profiled)
    fc3_kernel<<<NB, 128>>>(b2, W3, b3, out);                                // 5
}

// round 17
// speedup vs baseline: 1.4111x; 1.1250x over previous
#include <cuda_runtime.h>
#include <cuda_fp16.h>
#include <cstdint>

// ---------------------------------------------------------------------------
// CorrelationHead: corr(P=16, DIL=2, H=7, C=256) -> FC(12544->1024) ReLU
//                  -> FC(1024->1024) ReLU -> FC(1024->4)
// 625 live features = same-parity entries of per-RoI Gram X1[49,256]X2^T.
// R17: both FC GEMMs now fp16 operands / fp32 accumulate (m16n8k16).
// corr emits fp16 compacted features; W1 gather emits fp16. One shared
// fp16 GEMM template (KLEN, KROW). FC1 z=2 + reduce1 -> fp16; FC2 z=2,
// reduce fused into fc3.
// ---------------------------------------------------------------------------

#define NB   1024
#define KC   640
#define KCV  625
#define REP  1024
#define CHUNKF 1568              // 32 ch * 49 pos floats per patch chunk
#define NBREP (NB * REP)

// scratch (static device globals; no allocation allowed)
__device__ __half g_corrh[NB * KC];      // compacted correlation (fp16)
__device__ __half g_W1h  [REP * KC];     // gathered W1 columns (fp16)
__device__ __half g_W2h  [REP * REP];    // W2 (fp16)
__device__ __half g_out1h[NB * REP];     // FC1 out (fp16)
__device__ float  g_split[2 * NB * REP]; // split-K partials (fp32), reused

// ---------------------------------------------------------------------------
__device__ __forceinline__ float tf32r(float x)
{
    unsigned u;
    asm("cvt.rna.tf32.f32 %0, %1;" : "=r"(u) : "f"(x));
    return __uint_as_float(u);
}
__device__ __forceinline__ unsigned tf32u(float x)
{
    unsigned u;
    asm("cvt.rna.tf32.f32 %0, %1;" : "=r"(u) : "f"(x));
    return u;
}

// compact index u -> (r1, r2) position pair  (class-major ordering)
__device__ __forceinline__ void u_decode(int u, int& r1, int& r2)
{
    int c, rem;
    if      (u < 256) { c = 0; rem = u; }
    else if (u < 400) { c = 1; rem = u - 256; }
    else if (u < 544) { c = 2; rem = u - 400; }
    else              { c = 3; rem = u - 544; }
    int pi = c >> 1, pj = c & 1;
    int ni = pi ? 3 : 4, nj = pj ? 3 : 4;
    int nc = ni * nj;
    int al = rem / nc, bl = rem - al * nc;
    int i  = 2 * (al / nj) + pi, j  = 2 * (al % nj) + pj;
    int i2 = 2 * (bl / nj) + pi, j2 = 2 * (bl % nj) + pj;
    r1 = i * 7 + j;
    r2 = i2 * 7 + j2;
}

__device__ __forceinline__ void cpa16(void* s, const void* g)
{
    unsigned sa = (unsigned)__cvta_generic_to_shared(s);
    asm volatile("cp.async.cg.shared.global [%0], [%1], 16;" :: "r"(sa), "l"(g));
}

__device__ __forceinline__ void mma8(float* c, const unsigned* a, const unsigned* b)
{
    asm volatile(
        "mma.sync.aligned.m16n8k8.row.col.f32.tf32.tf32.f32 "
        "{%0,%1,%2,%3}, {%4,%5,%6,%7}, {%8,%9}, {%0,%1,%2,%3};\n"
        : "+f"(c[0]), "+f"(c[1]), "+f"(c[2]), "+f"(c[3])
        : "r"(a[0]), "r"(a[1]), "r"(a[2]), "r"(a[3]), "r"(b[0]), "r"(b[1]));
}

__device__ __forceinline__ void mma16h(float* c, const unsigned* a, const unsigned* b)
{
    asm volatile(
        "mma.sync.aligned.m16n8k16.row.col.f32.f16.f16.f32 "
        "{%0,%1,%2,%3}, {%4,%5,%6,%7}, {%8,%9}, {%0,%1,%2,%3};\n"
        : "+f"(c[0]), "+f"(c[1]), "+f"(c[2]), "+f"(c[3])
        : "r"(a[0]), "r"(a[1]), "r"(a[2]), "r"(a[3]), "r"(b[0]), "r"(b[1]));
}

__device__ __forceinline__ void ldm4(unsigned* r, unsigned saddr)
{
    asm volatile(
        "ldmatrix.sync.aligned.m8n8.x4.shared.b16 {%0,%1,%2,%3}, [%4];"
        : "=r"(r[0]), "=r"(r[1]), "=r"(r[2]), "=r"(r[3]) : "r"(saddr));
}

// ---------------------------------------------------------------------------
// Kernel 1: FUSED corr + prep.  grid 3328 x 128 threads.
//   blocks [0,1024)    : correlation (padded 64x64 Gram, 2-deep pipeline)
//   blocks [1024,2304) : W1 column gather (fp16)
//   blocks [2304,3328) : W2 fp16 convert
// ---------------------------------------------------------------------------
#define CORR_SMEM ((4 * CHUNKF + 16) * 4)   // 25,152 B

__global__ void __launch_bounds__(128)
fused_corr_prep_kernel(const float* __restrict__ p1,
                       const float* __restrict__ p2,
                       const float* __restrict__ W1,
                       const float* __restrict__ W2)
{
    const int bx  = blockIdx.x;
    const int tid = threadIdx.x;

    if (bx >= 2304) {                      // ---- W2 fp16 convert ----
        int base = (bx - 2304) * 256;
#pragma unroll
        for (int it = 0; it < 2; it++) {
            int q = base + it * 128 + tid;
            if (q < REP * REP / 4) {
                float4 v = ((const float4*)W2)[q];
                __half2* dst = (__half2*)g_W2h + q * 2;
                dst[0] = __floats2half2_rn(v.x, v.y);
                dst[1] = __floats2half2_rn(v.z, v.w);
            }
        }
        return;
    }
    if (bx >= 1024) {                      // ---- W1 gather (fp16) ----
        int base = (bx - 1024) * 512;
#pragma unroll
        for (int it = 0; it < 4; it++) {
            int idx = base + it * 128 + tid;
            if (idx < REP * KC) {
                int n = idx / KC;
                int u = idx - n * KC;
                float val = 0.f;
                if (u < KCV) {
                    int r1, r2;
                    u_decode(u, r1, r2);
                    int i = r1 / 7, j = r1 - 7 * i;
                    int i2 = r2 / 7, j2 = r2 - 7 * i2;
                    int ph = ((i2 - i) + 14) >> 1;
                    int pw = ((j2 - j) + 14) >> 1;
                    int col = (ph * 16 + pw) * 49 + r1;
                    val = W1[n * 12544 + col];
                }
                g_W1h[idx] = __float2half_rn(val);
            }
        }
        return;
    }

    // ---- correlation ----
    extern __shared__ float smem[];

    const int b    = bx;
    const int lane = tid & 31, warp = tid >> 5;
    const int wm   = warp & 1, wn = warp >> 1;
    const int grp  = lane >> 2, qd = lane & 3;
    const float* g1 = p1 + (size_t)b * 12544;
    const float* g2 = p2 + (size_t)b * 12544;

    auto issue = [&](int c) {
        float* s1 = smem + (c & 1) * 2 * CHUNKF;
        float* s2 = s1 + CHUNKF;
        const float* q1 = g1 + c * CHUNKF;
        const float* q2 = g2 + c * CHUNKF;
#pragma unroll
        for (int it = 0; it < 4; it++) {
            int f = tid + it * 128;
            if (f < 392) {
                cpa16(&s1[f * 4], q1 + f * 4);
                cpa16(&s2[f * 4], q2 + f * 4);
            }
        }
        asm volatile("cp.async.commit_group;" ::: "memory");
    };

    issue(0);

    float acc[2][4][4];
#pragma unroll
    for (int mt = 0; mt < 2; mt++)
#pragma unroll
        for (int nt = 0; nt < 4; nt++)
#pragma unroll
            for (int t = 0; t < 4; t++) acc[mt][nt][t] = 0.f;

    for (int c = 0; c < 8; c++) {
        if (c < 7) {
            issue(c + 1);
            asm volatile("cp.async.wait_group 1;" ::: "memory");
        } else {
            asm volatile("cp.async.wait_group 0;" ::: "memory");
        }
        __syncthreads();

        const float* s1 = smem + (c & 1) * 2 * CHUNKF;
        const float* s2 = s1 + CHUNKF;

#pragma unroll
        for (int k8 = 0; k8 < 32; k8 += 8) {
            unsigned af[2][4], bf[4][2];
            const float* k0 = s1 + (k8 + qd) * 49;
            const float* k4 = s1 + (k8 + qd + 4) * 49;
#pragma unroll
            for (int mt = 0; mt < 2; mt++) {
                int r0 = wm * 32 + mt * 16 + grp;
                af[mt][0] = tf32u(k0[r0]);
                af[mt][1] = tf32u(k0[r0 + 8]);
                af[mt][2] = tf32u(k4[r0]);
                af[mt][3] = tf32u(k4[r0 + 8]);
            }
            const float* j0 = s2 + (k8 + qd) * 49;
            const float* j4 = s2 + (k8 + qd + 4) * 49;
#pragma unroll
            for (int nt = 0; nt < 4; nt++) {
                int c0 = wn * 32 + nt * 8 + grp;
                bf[nt][0] = tf32u(j0[c0]);
                bf[nt][1] = tf32u(j4[c0]);
            }
#pragma unroll
            for (int mt = 0; mt < 2; mt++)
#pragma unroll
                for (int nt = 0; nt < 4; nt++)
                    mma8(acc[mt][nt], af[mt], bf[nt]);
        }
        __syncthreads();
    }

    __half* gc = g_corrh + (size_t)b * KC;
    if (tid < KC - KCV) gc[KCV + tid] = __float2half_rn(0.f);
#pragma unroll
    for (int mt = 0; mt < 2; mt++) {
#pragma unroll
        for (int nt = 0; nt < 4; nt++) {
#pragma unroll
            for (int t = 0; t < 4; t++) {
                int r  = wm * 32 + mt * 16 + grp + (t >> 1) * 8;
                int cc = wn * 32 + nt * 8 + qd * 2 + (t & 1);
                if (r < 49 && cc < 49) {
                    int i = r / 7,  j = r - 7 * i;
                    int i2 = cc / 7, j2 = cc - 7 * i2;
                    if ((((i ^ i2) | (j ^ j2)) & 1) == 0) {
                        int pi = i & 1, pj = j & 1;
                        int nj = pj ? 3 : 4;
                        int nc = (pi ? 3 : 4) * nj;
                        int off = pi ? (pj ? 544 : 400) : (pj ? 256 : 0);
                        int al = (i >> 1) * nj + (j >> 1);
                        int bl = (i2 >> 1) * nj + (j2 >> 1);
                        gc[off + al * nc + bl] = __float2half_rn(acc[mt][nt][t]);
                    }
                }
            }
        }
    }
}

// ---------------------------------------------------------------------------
// Kernel 2/4: shared fp16 GEMM. 64x64 tile, BK=64 halves, 256 thr, 8 warps
// (2x4), warp tile 32x16 (2x2 m16n8k16), ldmatrix, 3-stage cp.async,
// split-K via blockIdx.z. smem rows padded to 72 halves. Raw fp32 partials
// to g_split[z].
// MODE 0 (FC1): A=g_corrh, B=g_W1h,  KROW=KC.
// MODE 1 (FC2): A=g_out1h, B=g_W2h, KROW=REP.
// ---------------------------------------------------------------------------
#define HSTR 72
#define HSTG (64 * HSTR)                     // halves per matrix per stage
#define GEMM_SMEM (3 * 2 * HSTG * 2)         // 3 stages x (A+B) x 2B = 55,296 B

template <int KLEN, int MODE>
__global__ void __launch_bounds__(256)
gemm_fp16_kernel()
{
    const int KROW = (MODE == 0) ? KC : REP;
    const int kofs = blockIdx.z * KLEN;
    const __half* A  = ((MODE == 0) ? g_corrh : g_out1h) + kofs;
    const __half* Bm = ((MODE == 0) ? g_W1h   : g_W2h  ) + kofs;
    float*        Cm = g_split + (size_t)blockIdx.z * NBREP;

    extern __shared__ __half smh[];
    const unsigned smu = (unsigned)__cvta_generic_to_shared(smh);

    const int tid  = threadIdx.x;
    const int warp = tid >> 5, lane = tid & 31;
    const int wm   = warp & 1, wn = warp >> 1;      // 2 x 4 warp grid
    const int grp  = lane >> 2, qd = lane & 3;

    // loader: 64 rows x 64 halves per matrix per stage; thread: 2+2 cpa16
    const int lrow = tid >> 2;            // 0..63
    const int hc0  = (tid & 3) * 16;      // half offset 0,16,32,48
    const __half* Ag = A  + (size_t)(blockIdx.y * 64 + lrow) * KROW + hc0;
    const __half* Bg = Bm + (size_t)(blockIdx.x * 64 + lrow) * KROW + hc0;

    // ldmatrix lane addressing: row = base + (lane&15), 16B col = (lane>>4)
    const int lrow16 = lane & 15;
    const int lhb    = (lane >> 4) * 16;  // byte offset within k16 block
    const unsigned aofs0 = (unsigned)(wm * 32 + lrow16) * (HSTR * 2) + lhb;
    const unsigned aofs1 = aofs0 + 16 * HSTR * 2;
    const unsigned bofs  = (unsigned)(wn * 16 + lrow16) * (HSTR * 2) + lhb;

    float acc[2][2][4];
#pragma unroll
    for (int mt = 0; mt < 2; mt++)
#pragma unroll
        for (int nt = 0; nt < 2; nt++)
#pragma unroll
            for (int t = 0; t < 4; t++) acc[mt][nt][t] = 0.f;

    const int NT = KLEN / 64;

    auto issue = [&](int kt) {
        if (kt < NT) {
            __half* as = smh + (kt % 3) * 2 * HSTG;
            __half* bs = as + HSTG;
            cpa16(&as[lrow * HSTR + hc0],     Ag + kt * 64);
            cpa16(&as[lrow * HSTR + hc0 + 8], Ag + kt * 64 + 8);
            cpa16(&bs[lrow * HSTR + hc0],     Bg + kt * 64);
            cpa16(&bs[lrow * HSTR + hc0 + 8], Bg + kt * 64 + 8);
        }
        asm volatile("cp.async.commit_group;" ::: "memory");
    };

    issue(0); issue(1);

    for (int kt = 0; kt < NT; kt++) {
        asm volatile("cp.async.wait_group 1;" ::: "memory");
        __syncthreads();
        issue(kt + 2);

        const unsigned sa = smu + (unsigned)(kt % 3) * 2 * HSTG * 2;
        const unsigned sb = sa + HSTG * 2;
#pragma unroll
        for (int s = 0; s < 4; s++) {       // four k16 steps per BK=64
            unsigned af[2][4], t[4];
            ldm4(af[0], sa + aofs0 + s * 32);
            ldm4(af[1], sa + aofs1 + s * 32);
            ldm4(t,     sb + bofs  + s * 32);
            unsigned bf[2][2] = { {t[0], t[2]}, {t[1], t[3]} };
#pragma unroll
            for (int mt = 0; mt < 2; mt++)
#pragma unroll
                for (int nt = 0; nt < 2; nt++)
                    mma16h(acc[mt][nt], af[mt], bf[nt]);
        }
    }

#pragma unroll
    for (int mt = 0; mt < 2; mt++) {
#pragma unroll
        for (int nt = 0; nt < 2; nt++) {
            int rg = blockIdx.y * 64 + wm * 32 + mt * 16 + grp;
            int cg = blockIdx.x * 64 + wn * 16 + nt * 8 + qd * 2;
#pragma unroll
            for (int h = 0; h < 2; h++) {
                float v0 = acc[mt][nt][h * 2 + 0];
                float v1 = acc[mt][nt][h * 2 + 1];
                *(float2*)&Cm[(size_t)(rg + h * 8) * 1024 + cg] = make_float2(v0, v1);
            }
        }
    }
}

// ---------------------------------------------------------------------------
// Kernel 3: FC1 split-K reduce + bias + ReLU -> fp16 g_out1h
// ---------------------------------------------------------------------------
__global__ void __launch_bounds__(256)
reduce_fc1_kernel(const float* __restrict__ b1)
{
    int q = blockIdx.x * 256 + threadIdx.x;     // float4 index
    if (q >= NBREP / 4) return;
    float4 a = ((const float4*)g_split)[q];
    float4 b = ((const float4*)(g_split + NBREP))[q];
    float4 bb = *(const float4*)&b1[(q & 255) * 4];
    float rx = fmaxf(a.x + b.x + bb.x, 0.f);
    float ry = fmaxf(a.y + b.y + bb.y, 0.f);
    float rz = fmaxf(a.z + b.z + bb.z, 0.f);
    float rw = fmaxf(a.w + b.w + bb.w, 0.f);
    __half2* dst = (__half2*)g_out1h + q * 2;
    dst[0] = __floats2half2_rn(rx, ry);
    dst[1] = __floats2half2_rn(rz, rw);
}

// ---------------------------------------------------------------------------
// Kernel 5: FC3 fused with FC2 2-way split-K reduce + bias + ReLU.
// ---------------------------------------------------------------------------
__global__ void __launch_bounds__(128)
fc3_kernel(const float* __restrict__ b2, const float* __restrict__ W3,
           const float* __restrict__ b3, float* __restrict__ out)
{
    __shared__ float xs[1024];
    int b    = blockIdx.x;
    int tid  = threadIdx.x;
    int warp = tid >> 5;
    int lane = tid & 31;

    const float* s0 = g_split + (size_t)b * 1024;
#pragma unroll
    for (int it = 0; it < 2; it++) {
        int q = tid + it * 128;           // float4 index 0..255
        float4 a = ((const float4*)s0)[q];
        float4 c = ((const float4*)(s0 + NBREP))[q];
        float4 bb = *(const float4*)&b2[q * 4];
        float4 r;
        r.x = fmaxf(a.x + c.x + bb.x, 0.f);
        r.y = fmaxf(a.y + c.y + bb.y, 0.f);
        r.z = fmaxf(a.z + c.z + bb.z, 0.f);
        r.w = fmaxf(a.w + c.w + bb.w, 0.f);
        *(float4*)&xs[q * 4] = r;
    }
    __syncthreads();

    const float* w = W3 + warp * 1024;
    float acc = 0.f;
#pragma unroll 8
    for (int k = lane; k < 1024; k += 32) acc += xs[k] * w[k];
#pragma unroll
    for (int off = 16; off; off >>= 1)
        acc += __shfl_xor_sync(0xffffffffu, acc, off);
    if (lane == 0) out[b * 4 + warp] = acc + b3[warp];
}

// ---------------------------------------------------------------------------
// launch  (gemm2 fp16 is the 4th launch -> it gets profiled)
// ---------------------------------------------------------------------------
extern "C" void kernel_launch(void* const* d_in, const int* in_sizes, int n_in,
                              void* d_out, int out_size)
{
    const float* p1 = (const float*)d_in[0];
    const float* p2 = (const float*)d_in[1];
    const float* W1 = (const float*)d_in[2];
    const float* b1 = (const float*)d_in[3];
    const float* W2 = (const float*)d_in[4];
    const float* b2 = (const float*)d_in[5];
    const float* W3 = (const float*)d_in[6];
    const float* b3 = (const float*)d_in[7];
    float* out = (float*)d_out;
    (void)in_sizes; (void)n_in; (void)out_size;

    cudaFuncSetAttribute(fused_corr_prep_kernel,
                         cudaFuncAttributeMaxDynamicSharedMemorySize, CORR_SMEM);
    cudaFuncSetAttribute(gemm_fp16_kernel<320, 0>,
                         cudaFuncAttributeMaxDynamicSharedMemorySize, GEMM_SMEM);
    cudaFuncSetAttribute(gemm_fp16_kernel<512, 1>,
                         cudaFuncAttributeMaxDynamicSharedMemorySize, GEMM_SMEM);

    fused_corr_prep_kernel<<<3328, 128, CORR_SMEM>>>(p1, p2, W1, W2);        // 1
    gemm_fp16_kernel<320, 0><<<dim3(16, 16, 2), 256, GEMM_SMEM>>>();         // 2
    reduce_fc1_kernel<<<NBREP / 4 / 256, 256>>>(b1);                         // 3
    gemm_fp16_kernel<512, 1><<<dim3(16, 16, 2), 256, GEMM_SMEM>>>();         // 4 (profiled)
    fc3_kernel<<<NB, 128>>>(b2, W3, b3, out);                                // 5
}